// round 1
// baseline (speedup 1.0000x reference)
#include <cuda_runtime.h>

#define NN 50000
#define EE 800000
#define DD 128
#define LL 3
#define JKD (LL*DD)   // 384
#define H2 64

// ---------------- scratch (device globals: no allocation allowed) ----------------
__device__ int   g_deg[NN];
__device__ int   g_off[NN + 1];
__device__ int   g_cur[NN];
__device__ int   g_csr[EE];
__device__ float g_agg[(size_t)NN * DD];          // 25.6 MB
__device__ float g_jk[(size_t)NN * JKD];          // 76.8 MB (layer outputs, JK-concat layout)
__device__ int   g_is64;

// ---------------- edge-index dtype detection (int64 vs int32) ----------------
__global__ void detect_kernel(const int* __restrict__ ei32) {
    if (threadIdx.x == 0 && blockIdx.x == 0) {
        int nz = 0;
        // if int64: words 1,3,5,... are high halves of values < 2^31 -> all zero
        for (int i = 1; i < 64; i += 2) nz |= ei32[i];
        g_is64 = (nz == 0) ? 1 : 0;
    }
}

__device__ __forceinline__ void load_edge(const void* ei, int e, int& src, int& dst) {
    if (g_is64) {
        const long long* p = (const long long*)ei;
        src = (int)p[e];
        dst = (int)p[EE + e];
    } else {
        const int* p = (const int*)ei;
        src = p[e];
        dst = p[EE + e];
    }
}

// ---------------- CSR build ----------------
__global__ void zero_deg_kernel() {
    int i = blockIdx.x * blockDim.x + threadIdx.x;
    if (i < NN) g_deg[i] = 0;
}

__global__ void deg_kernel(const void* __restrict__ ei) {
    int e = blockIdx.x * blockDim.x + threadIdx.x;
    if (e < EE) {
        int src, dst;
        load_edge(ei, e, src, dst);
        atomicAdd(&g_deg[dst], 1);
    }
}

__global__ void scan_kernel() {  // single block, 1024 threads
    __shared__ int ssum[1024];
    const int CH = (NN + 1023) / 1024;  // 49
    int t = threadIdx.x;
    int b = t * CH;
    int e2 = min(b + CH, NN);
    int s = 0;
    for (int i = b; i < e2; i++) s += g_deg[i];
    ssum[t] = s;
    __syncthreads();
    for (int d = 1; d < 1024; d <<= 1) {
        int v = (t >= d) ? ssum[t - d] : 0;
        __syncthreads();
        ssum[t] += v;
        __syncthreads();
    }
    int run = ssum[t] - s;  // exclusive prefix
    for (int i = b; i < e2; i++) {
        g_off[i] = run;
        g_cur[i] = run;
        run += g_deg[i];
    }
    if (t == 1023) g_off[NN] = ssum[1023];
}

__global__ void fill_kernel(const void* __restrict__ ei) {
    int e = blockIdx.x * blockDim.x + threadIdx.x;
    if (e < EE) {
        int src, dst;
        load_edge(ei, e, src, dst);
        int pos = atomicAdd(&g_cur[dst], 1);
        g_csr[pos] = src;
    }
}

// ---------------- mean aggregation: warp per node, atomic-free ----------------
__global__ void agg_kernel(const float* __restrict__ x, int layer) {
    int warp = (blockIdx.x * blockDim.x + threadIdx.x) >> 5;
    int lane = threadIdx.x & 31;
    if (warp >= NN) return;
    const float* in;
    int stride;
    if (layer == 0) { in = x; stride = DD; }
    else            { in = g_jk + (layer - 1) * DD; stride = JKD; }

    int node = warp;
    int beg = g_off[node], end = g_off[node + 1];
    float4 acc = make_float4(0.f, 0.f, 0.f, 0.f);
    for (int e = beg; e < end; e += 32) {
        int m = min(32, end - e);
        int srcn = (lane < m) ? g_csr[e + lane] : 0;
        for (int i = 0; i < m; i++) {
            int s = __shfl_sync(0xffffffffu, srcn, i);
            const float4 v = *reinterpret_cast<const float4*>(in + (size_t)s * stride + lane * 4);
            acc.x += v.x; acc.y += v.y; acc.z += v.z; acc.w += v.w;
        }
    }
    int deg = end - beg;
    float inv = 1.0f / (float)max(deg, 1);
    float4 o = make_float4(acc.x * inv, acc.y * inv, acc.z * inv, acc.w * inv);
    *reinterpret_cast<float4*>(&g_agg[(size_t)node * DD + lane * 4]) = o;
}

// ---------------- fused layer GEMM: [agg|h] @ [Wl;Wr] + bias + BN + ReLU ----------------
// block = 256 threads (8 warps). Block tile: 64 nodes x 128 cols.
// warp handles 8 nodes; lane handles 4 cols (lane*4..+3). K = 256.
__global__ void layer_kernel(const float* __restrict__ x, int layer,
                             const float* __restrict__ Wl, const float* __restrict__ bl,
                             const float* __restrict__ Wr, const float* __restrict__ gamma,
                             const float* __restrict__ beta, const float* __restrict__ rmean,
                             const float* __restrict__ rvar) {
    extern __shared__ float sm[];
    float* Ws = sm;                 // [256][128] = 32768 floats
    float* Is = sm + 256 * 128;     // [64][256]  = 16384 floats

    const float* in;
    int stride;
    if (layer == 0) { in = x; stride = DD; }
    else            { in = g_jk + (layer - 1) * DD; stride = JKD; }

    int tid = threadIdx.x;
    int tileBase = blockIdx.x * 64;

    const float* WlL = Wl + (size_t)layer * DD * DD;
    const float* WrL = Wr + (size_t)layer * DD * DD;

    // weights: 8192 float4
    for (int idx = tid; idx < 8192; idx += 256) {
        int k  = idx >> 5;   // row
        int j4 = idx & 31;   // float4 col
        float4 v;
        if (k < 128) v = *reinterpret_cast<const float4*>(WlL + (size_t)k * DD + j4 * 4);
        else         v = *reinterpret_cast<const float4*>(WrL + (size_t)(k - 128) * DD + j4 * 4);
        *reinterpret_cast<float4*>(Ws + (size_t)idx * 4) = v;
    }
    // inputs: 4096 float4 (64 rows x 64 float4); k<128 -> agg, else h
    for (int idx = tid; idx < 4096; idx += 256) {
        int m  = idx >> 6;
        int k4 = idx & 63;
        int node = tileBase + m;
        float4 v = make_float4(0.f, 0.f, 0.f, 0.f);
        if (node < NN) {
            if (k4 < 32) v = *reinterpret_cast<const float4*>(g_agg + (size_t)node * DD + k4 * 4);
            else         v = *reinterpret_cast<const float4*>(in + (size_t)node * stride + (k4 - 32) * 4);
        }
        *reinterpret_cast<float4*>(Is + (size_t)m * 256 + k4 * 4) = v;
    }
    __syncthreads();

    int warp = tid >> 5, lane = tid & 31;
    int wbase = warp * 8;
    float4 acc[8];
#pragma unroll
    for (int m = 0; m < 8; m++) acc[m] = make_float4(0.f, 0.f, 0.f, 0.f);

    const float* wsp = Ws + lane * 4;
#pragma unroll 4
    for (int k = 0; k < 256; k++) {
        float4 w = *reinterpret_cast<const float4*>(wsp + (size_t)k * 128);
#pragma unroll
        for (int m = 0; m < 8; m++) {
            float v = Is[(size_t)(wbase + m) * 256 + k];
            acc[m].x += v * w.x; acc[m].y += v * w.y;
            acc[m].z += v * w.z; acc[m].w += v * w.w;
        }
    }

    // epilogue: fold bias + BN into per-column affine, then ReLU
    int j0 = lane * 4;
    float sc[4], sh[4];
#pragma unroll
    for (int c = 0; c < 4; c++) {
        int j = layer * DD + j0 + c;
        float s = gamma[j] * rsqrtf(rvar[j] + 1e-5f);
        sc[c] = s;
        sh[c] = (bl[j] - rmean[j]) * s + beta[j];
    }
#pragma unroll
    for (int m = 0; m < 8; m++) {
        int node = tileBase + wbase + m;
        if (node < NN) {
            float4 o;
            o.x = fmaxf(acc[m].x * sc[0] + sh[0], 0.f);
            o.y = fmaxf(acc[m].y * sc[1] + sh[1], 0.f);
            o.z = fmaxf(acc[m].z * sc[2] + sh[2], 0.f);
            o.w = fmaxf(acc[m].w * sc[3] + sh[3], 0.f);
            *reinterpret_cast<float4*>(&g_jk[(size_t)node * JKD + layer * DD + j0]) = o;
        }
    }
}

// ---------------- classifier: relu(jk @ Wc1 + bc1) @ Wc2 + bc2 ----------------
// block = 256 threads = 16 groups of 16; group -> one node; thread -> 4 of 64 hidden cols.
#define JSTR 388
__global__ void cls_kernel(const float* __restrict__ Wc1, const float* __restrict__ bc1,
                           const float* __restrict__ Wc2, const float* __restrict__ bc2,
                           float* __restrict__ out) {
    extern __shared__ float sm[];
    float* W1s = sm;                       // 384*64 = 24576
    float* Js  = sm + 24576;               // 16*388 = 6208 (padded rows)
    float* Zs  = sm + 24576 + 16 * JSTR;   // 16*64 = 1024

    int tid = threadIdx.x;
    int nodeBase = blockIdx.x * 16;

    for (int idx = tid; idx < 6144; idx += 256)  // 24576/4 float4
        *reinterpret_cast<float4*>(W1s + (size_t)idx * 4) =
            *reinterpret_cast<const float4*>(Wc1 + (size_t)idx * 4);

    for (int idx = tid; idx < 16 * 96; idx += 256) {  // 16 rows x 96 float4
        int m = idx / 96, k4 = idx % 96;
        int node = nodeBase + m;
        float4 v = make_float4(0.f, 0.f, 0.f, 0.f);
        if (node < NN) v = *reinterpret_cast<const float4*>(g_jk + (size_t)node * JKD + k4 * 4);
        *reinterpret_cast<float4*>(Js + (size_t)m * JSTR + k4 * 4) = v;
    }
    __syncthreads();

    int g = tid >> 4, tg = tid & 15;
    float4 acc = make_float4(0.f, 0.f, 0.f, 0.f);
    const float* jrow = Js + (size_t)g * JSTR;
#pragma unroll 4
    for (int k = 0; k < JKD; k++) {
        float v = jrow[k];
        float4 w = *reinterpret_cast<const float4*>(W1s + (size_t)k * 64 + tg * 4);
        acc.x += v * w.x; acc.y += v * w.y; acc.z += v * w.z; acc.w += v * w.w;
    }
    float4 b = *reinterpret_cast<const float4*>(bc1 + tg * 4);
    Zs[g * 64 + tg * 4 + 0] = fmaxf(acc.x + b.x, 0.f);
    Zs[g * 64 + tg * 4 + 1] = fmaxf(acc.y + b.y, 0.f);
    Zs[g * 64 + tg * 4 + 2] = fmaxf(acc.z + b.z, 0.f);
    Zs[g * 64 + tg * 4 + 3] = fmaxf(acc.w + b.w, 0.f);
    __syncthreads();

    if (tg < 2) {
        int node = nodeBase + g;
        if (node < NN) {
            float sum = bc2[tg];
#pragma unroll
            for (int j = 0; j < 64; j++) sum += Zs[g * 64 + j] * Wc2[j * 2 + tg];
            out[(size_t)node * 2 + tg] = sum;
        }
    }
}

// ---------------- host ----------------
extern "C" void kernel_launch(void* const* d_in, const int* in_sizes, int n_in,
                              void* d_out, int out_size) {
    const float* x     = (const float*)d_in[0];
    const void*  ei    = d_in[1];
    const float* Wl    = (const float*)d_in[2];
    const float* bl    = (const float*)d_in[3];
    const float* Wr    = (const float*)d_in[4];
    const float* gamma = (const float*)d_in[5];
    const float* beta  = (const float*)d_in[6];
    const float* rmean = (const float*)d_in[7];
    const float* rvar  = (const float*)d_in[8];
    const float* Wc1   = (const float*)d_in[9];
    const float* bc1   = (const float*)d_in[10];
    const float* Wc2   = (const float*)d_in[11];
    const float* bc2   = (const float*)d_in[12];
    float* out = (float*)d_out;

    cudaFuncSetAttribute(layer_kernel, cudaFuncAttributeMaxDynamicSharedMemorySize, 196608);
    cudaFuncSetAttribute(cls_kernel,   cudaFuncAttributeMaxDynamicSharedMemorySize, 127232);

    detect_kernel<<<1, 32>>>((const int*)ei);
    zero_deg_kernel<<<(NN + 255) / 256, 256>>>();
    deg_kernel<<<(EE + 255) / 256, 256>>>(ei);
    scan_kernel<<<1, 1024>>>();
    fill_kernel<<<(EE + 255) / 256, 256>>>(ei);

    for (int layer = 0; layer < LL; layer++) {
        agg_kernel<<<(NN * 32 + 255) / 256, 256>>>(x, layer);
        layer_kernel<<<(NN + 63) / 64, 256, 196608>>>(x, layer, Wl, bl, Wr,
                                                      gamma, beta, rmean, rvar);
    }
    cls_kernel<<<(NN + 15) / 16, 256, 127232>>>(Wc1, bc1, Wc2, bc2, out);
}

// round 3
// speedup vs baseline: 1.0940x; 1.0940x over previous
#include <cuda_runtime.h>

#define NN 50000
#define EE 800000
#define DD 128
#define LL 3
#define JKD (LL*DD)   // 384
#define H2 64
#define NB 196        // ceil(NN/256)

// ---------------- scratch (device globals: no allocation allowed) ----------------
__device__ int   g_deg[NN];
__device__ int   g_off[NN + 1];
__device__ int   g_cur[NN];
__device__ int   g_csr[EE];
__device__ int   g_bsum[NB];
__device__ int   g_bpre[NB];
__device__ float g_agg[(size_t)NN * DD];          // 25.6 MB
__device__ float g_jk[(size_t)NN * JKD];          // 76.8 MB (layer outputs, JK layout)
__device__ int   g_is64;

// ---------------- f32x2 packed helpers ----------------
__device__ __forceinline__ void ffma2(unsigned long long& d, unsigned long long a,
                                      unsigned long long b) {
    asm("fma.rn.f32x2 %0, %1, %2, %0;" : "+l"(d) : "l"(a), "l"(b));
}
__device__ __forceinline__ unsigned long long splat2(float v) {
    unsigned long long r;
    asm("mov.b64 %0, {%1, %1};" : "=l"(r) : "f"(v));
    return r;
}
__device__ __forceinline__ float2 unpack2(unsigned long long p) {
    float2 r;
    asm("mov.b64 {%0, %1}, %2;" : "=f"(r.x), "=f"(r.y) : "l"(p));
    return r;
}

// ---------------- edge-index dtype detection (int64 vs int32) ----------------
__global__ void detect_kernel(const int* __restrict__ ei32) {
    if (threadIdx.x == 0 && blockIdx.x == 0) {
        int nz = 0;
        for (int i = 1; i < 64; i += 2) nz |= ei32[i];
        g_is64 = (nz == 0) ? 1 : 0;
    }
}

__device__ __forceinline__ void load_edge(const void* ei, int e, int& src, int& dst) {
    if (g_is64) {
        const long long* p = (const long long*)ei;
        src = (int)p[e];
        dst = (int)p[EE + e];
    } else {
        const int* p = (const int*)ei;
        src = p[e];
        dst = p[EE + e];
    }
}

// ---------------- CSR build ----------------
__global__ void zero_deg_kernel() {
    int i = blockIdx.x * blockDim.x + threadIdx.x;
    if (i < NN) g_deg[i] = 0;
}

__global__ void deg_kernel(const void* __restrict__ ei) {
    int e = blockIdx.x * blockDim.x + threadIdx.x;
    if (e < EE) {
        int src, dst;
        load_edge(ei, e, src, dst);
        atomicAdd(&g_deg[dst], 1);
    }
}

// stage 1: per-block sums of degrees
__global__ void bsum_kernel() {
    __shared__ int s[256];
    int t = threadIdx.x;
    int i = blockIdx.x * 256 + t;
    s[t] = (i < NN) ? g_deg[i] : 0;
    __syncthreads();
    for (int d = 128; d > 0; d >>= 1) {
        if (t < d) s[t] += s[t + d];
        __syncthreads();
    }
    if (t == 0) g_bsum[blockIdx.x] = s[0];
}

// stage 2: scan the 196 block sums (one block)
__global__ void bscan_kernel() {
    __shared__ int s[256];
    int t = threadIdx.x;
    int v = (t < NB) ? g_bsum[t] : 0;
    s[t] = v;
    __syncthreads();
    for (int d = 1; d < 256; d <<= 1) {
        int u = (t >= d) ? s[t - d] : 0;
        __syncthreads();
        s[t] += u;
        __syncthreads();
    }
    if (t < NB) g_bpre[t] = s[t] - v;   // exclusive
    if (t == 255) g_off[NN] = s[255];
}

// stage 3: per-block exclusive scan + base
__global__ void offs_kernel() {
    __shared__ int s[256];
    int t = threadIdx.x;
    int i = blockIdx.x * 256 + t;
    int v = (i < NN) ? g_deg[i] : 0;
    s[t] = v;
    __syncthreads();
    for (int d = 1; d < 256; d <<= 1) {
        int u = (t >= d) ? s[t - d] : 0;
        __syncthreads();
        s[t] += u;
        __syncthreads();
    }
    if (i < NN) {
        int excl = s[t] - v + g_bpre[blockIdx.x];
        g_off[i] = excl;
        g_cur[i] = excl;
    }
}

__global__ void fill_kernel(const void* __restrict__ ei) {
    int e = blockIdx.x * blockDim.x + threadIdx.x;
    if (e < EE) {
        int src, dst;
        load_edge(ei, e, src, dst);
        int pos = atomicAdd(&g_cur[dst], 1);
        g_csr[pos] = src;
    }
}

// ---------------- mean aggregation: warp per node, atomic-free ----------------
__global__ void agg_kernel(const float* __restrict__ x, int layer) {
    int warp = (blockIdx.x * blockDim.x + threadIdx.x) >> 5;
    int lane = threadIdx.x & 31;
    if (warp >= NN) return;
    const float* in;
    int stride;
    if (layer == 0) { in = x; stride = DD; }
    else            { in = g_jk + (layer - 1) * DD; stride = JKD; }

    int node = warp;
    int beg = g_off[node], end = g_off[node + 1];
    float4 acc = make_float4(0.f, 0.f, 0.f, 0.f);
    for (int e = beg; e < end; e += 32) {
        int m = min(32, end - e);
        int srcn = (lane < m) ? g_csr[e + lane] : 0;
        for (int i = 0; i < m; i++) {
            int s = __shfl_sync(0xffffffffu, srcn, i);
            const float4 v = *reinterpret_cast<const float4*>(in + (size_t)s * stride + lane * 4);
            acc.x += v.x; acc.y += v.y; acc.z += v.z; acc.w += v.w;
        }
    }
    int deg = end - beg;
    float inv = 1.0f / (float)max(deg, 1);
    float4 o = make_float4(acc.x * inv, acc.y * inv, acc.z * inv, acc.w * inv);
    *reinterpret_cast<float4*>(&g_agg[(size_t)node * DD + lane * 4]) = o;
}

// ---------------- fused layer GEMM (f32x2 packed) ----------------
// block = 256 threads. Tile: 128 nodes x 128 cols, K=256 in 2 chunks of 128.
// thread = (node-group ng: 8 nodes) x (col-group cg: 8 cols) -> 32 packed acc.
// ISTR must keep rows 16B-aligned: 260 floats = 1040 B (multiple of 16).
#define ISTR 260
__global__ __launch_bounds__(256, 1)
void layer_kernel(const float* __restrict__ x, int layer,
                  const float* __restrict__ Wl, const float* __restrict__ bl,
                  const float* __restrict__ Wr, const float* __restrict__ gamma,
                  const float* __restrict__ beta, const float* __restrict__ rmean,
                  const float* __restrict__ rvar) {
    extern __shared__ float sm[];
    float* Ws = sm;                 // [128][128] = 16384 floats (per K-chunk)
    float* Is = sm + 16384;         // [128][ISTR] node-major, [agg(128)|h(128)] per row

    const float* in;
    int stride;
    if (layer == 0) { in = x; stride = DD; }
    else            { in = g_jk + (layer - 1) * DD; stride = JKD; }

    int tid = threadIdx.x;
    int tileBase = blockIdx.x * 128;

    // load Is: 128 rows x 64 float4
    for (int idx = tid; idx < 128 * 64; idx += 256) {
        int m = idx >> 6, k4 = idx & 63;
        int node = tileBase + m;
        float4 v = make_float4(0.f, 0.f, 0.f, 0.f);
        if (node < NN) {
            if (k4 < 32) v = *reinterpret_cast<const float4*>(g_agg + (size_t)node * DD + k4 * 4);
            else         v = *reinterpret_cast<const float4*>(in + (size_t)node * stride + (k4 - 32) * 4);
        }
        *reinterpret_cast<float4*>(Is + (size_t)m * ISTR + k4 * 4) = v;
    }

    const float* WlL = Wl + (size_t)layer * DD * DD;
    const float* WrL = Wr + (size_t)layer * DD * DD;

    int ng = tid >> 4, cg = tid & 15;
    unsigned long long acc[8][4];
#pragma unroll
    for (int n = 0; n < 8; n++)
#pragma unroll
        for (int p = 0; p < 4; p++) acc[n][p] = 0ull;

    for (int chunk = 0; chunk < 2; chunk++) {
        const float* Wsrc = chunk ? WrL : WlL;
        __syncthreads();   // Is ready (chunk0) / prior compute done (chunk1)
        for (int idx = tid; idx < 128 * 32; idx += 256)
            *reinterpret_cast<float4*>(Ws + (size_t)idx * 4) =
                *reinterpret_cast<const float4*>(Wsrc + (size_t)idx * 4);
        __syncthreads();

        const float* vbase = Is + (size_t)(ng * 8) * ISTR + chunk * 128;
        const float* wbase = Ws + cg * 8;
#pragma unroll 2
        for (int k = 0; k < 128; k++) {
            ulonglong2 wA = *reinterpret_cast<const ulonglong2*>(wbase + (size_t)k * 128);
            ulonglong2 wB = *reinterpret_cast<const ulonglong2*>(wbase + (size_t)k * 128 + 4);
#pragma unroll
            for (int n = 0; n < 8; n++) {
                unsigned long long vv = splat2(vbase[(size_t)n * ISTR + k]);
                ffma2(acc[n][0], vv, wA.x);
                ffma2(acc[n][1], vv, wA.y);
                ffma2(acc[n][2], vv, wB.x);
                ffma2(acc[n][3], vv, wB.y);
            }
        }
    }

    // epilogue: bias + BN folded into affine, ReLU, write into JK slice
    int c0 = cg * 8;
    float sc[8], sh[8];
#pragma unroll
    for (int c = 0; c < 8; c++) {
        int j = layer * DD + c0 + c;
        float s = gamma[j] * rsqrtf(rvar[j] + 1e-5f);
        sc[c] = s;
        sh[c] = (bl[j] - rmean[j]) * s + beta[j];
    }
#pragma unroll
    for (int n = 0; n < 8; n++) {
        int node = tileBase + ng * 8 + n;
        if (node < NN) {
            float o[8];
#pragma unroll
            for (int p = 0; p < 4; p++) {
                float2 u = unpack2(acc[n][p]);
                o[2 * p] = u.x; o[2 * p + 1] = u.y;
            }
            float4 r0, r1;
            r0.x = fmaxf(o[0] * sc[0] + sh[0], 0.f);
            r0.y = fmaxf(o[1] * sc[1] + sh[1], 0.f);
            r0.z = fmaxf(o[2] * sc[2] + sh[2], 0.f);
            r0.w = fmaxf(o[3] * sc[3] + sh[3], 0.f);
            r1.x = fmaxf(o[4] * sc[4] + sh[4], 0.f);
            r1.y = fmaxf(o[5] * sc[5] + sh[5], 0.f);
            r1.z = fmaxf(o[6] * sc[6] + sh[6], 0.f);
            r1.w = fmaxf(o[7] * sc[7] + sh[7], 0.f);
            float* dst = g_jk + (size_t)node * JKD + layer * DD + c0;
            *reinterpret_cast<float4*>(dst) = r0;
            *reinterpret_cast<float4*>(dst + 4) = r1;
        }
    }
}

// ---------------- classifier: relu(jk @ Wc1 + bc1) @ Wc2 + bc2 ----------------
#define JSTR 388
__global__ void cls_kernel(const float* __restrict__ Wc1, const float* __restrict__ bc1,
                           const float* __restrict__ Wc2, const float* __restrict__ bc2,
                           float* __restrict__ out) {
    extern __shared__ float sm[];
    float* W1s = sm;                       // 384*64 = 24576
    float* Js  = sm + 24576;               // 16*388 (row = 1552 B, 16B-aligned)
    float* Zs  = sm + 24576 + 16 * JSTR;   // 16*64

    int tid = threadIdx.x;
    int nodeBase = blockIdx.x * 16;

    for (int idx = tid; idx < 6144; idx += 256)
        *reinterpret_cast<float4*>(W1s + (size_t)idx * 4) =
            *reinterpret_cast<const float4*>(Wc1 + (size_t)idx * 4);

    for (int idx = tid; idx < 16 * 96; idx += 256) {
        int m = idx / 96, k4 = idx % 96;
        int node = nodeBase + m;
        float4 v = make_float4(0.f, 0.f, 0.f, 0.f);
        if (node < NN) v = *reinterpret_cast<const float4*>(g_jk + (size_t)node * JKD + k4 * 4);
        *reinterpret_cast<float4*>(Js + (size_t)m * JSTR + k4 * 4) = v;
    }
    __syncthreads();

    int g = tid >> 4, tg = tid & 15;
    unsigned long long a0 = 0ull, a1 = 0ull;
    const float* jrow = Js + (size_t)g * JSTR;
    const float* wp = W1s + tg * 4;
#pragma unroll 4
    for (int k = 0; k < JKD; k++) {
        unsigned long long vv = splat2(jrow[k]);
        ulonglong2 w2 = *reinterpret_cast<const ulonglong2*>(wp + (size_t)k * 64);
        ffma2(a0, vv, w2.x);
        ffma2(a1, vv, w2.y);
    }
    float2 u0 = unpack2(a0), u1 = unpack2(a1);
    float4 b = *reinterpret_cast<const float4*>(bc1 + tg * 4);
    Zs[g * 64 + tg * 4 + 0] = fmaxf(u0.x + b.x, 0.f);
    Zs[g * 64 + tg * 4 + 1] = fmaxf(u0.y + b.y, 0.f);
    Zs[g * 64 + tg * 4 + 2] = fmaxf(u1.x + b.z, 0.f);
    Zs[g * 64 + tg * 4 + 3] = fmaxf(u1.y + b.w, 0.f);
    __syncthreads();

    if (tg < 2) {
        int node = nodeBase + g;
        if (node < NN) {
            float sum = bc2[tg];
#pragma unroll
            for (int j = 0; j < 64; j++) sum += Zs[g * 64 + j] * Wc2[j * 2 + tg];
            out[(size_t)node * 2 + tg] = sum;
        }
    }
}

// ---------------- host ----------------
extern "C" void kernel_launch(void* const* d_in, const int* in_sizes, int n_in,
                              void* d_out, int out_size) {
    const float* x     = (const float*)d_in[0];
    const void*  ei    = d_in[1];
    const float* Wl    = (const float*)d_in[2];
    const float* bl    = (const float*)d_in[3];
    const float* Wr    = (const float*)d_in[4];
    const float* gamma = (const float*)d_in[5];
    const float* beta  = (const float*)d_in[6];
    const float* rmean = (const float*)d_in[7];
    const float* rvar  = (const float*)d_in[8];
    const float* Wc1   = (const float*)d_in[9];
    const float* bc1   = (const float*)d_in[10];
    const float* Wc2   = (const float*)d_in[11];
    const float* bc2   = (const float*)d_in[12];
    float* out = (float*)d_out;

    // smem: layer = (16384 + 128*260)*4 = 198656 B ; cls = 127232 B
    cudaFuncSetAttribute(layer_kernel, cudaFuncAttributeMaxDynamicSharedMemorySize, 198656);
    cudaFuncSetAttribute(cls_kernel,   cudaFuncAttributeMaxDynamicSharedMemorySize, 127232);

    detect_kernel<<<1, 32>>>((const int*)ei);
    zero_deg_kernel<<<(NN + 255) / 256, 256>>>();
    deg_kernel<<<(EE + 255) / 256, 256>>>(ei);
    bsum_kernel<<<NB, 256>>>();
    bscan_kernel<<<1, 256>>>();
    offs_kernel<<<NB, 256>>>();
    fill_kernel<<<(EE + 255) / 256, 256>>>(ei);

    for (int layer = 0; layer < LL; layer++) {
        agg_kernel<<<(NN * 32 + 255) / 256, 256>>>(x, layer);
        layer_kernel<<<(NN + 127) / 128, 256, 198656>>>(x, layer, Wl, bl, Wr,
                                                        gamma, beta, rmean, rvar);
    }
    cls_kernel<<<(NN + 15) / 16, 256, 127232>>>(Wc1, bc1, Wc2, bc2, out);
}

// round 4
// speedup vs baseline: 1.3524x; 1.2362x over previous
#include <cuda_runtime.h>

#define NN 50000
#define EE 800000
#define DD 128
#define LL 3
#define JKD (LL*DD)   // 384
#define H2 64
#define NB 196        // ceil(NN/256)

// ---------------- scratch (device globals: no allocation allowed) ----------------
__device__ int   g_deg[NN];
__device__ int   g_off[NN + 1];
__device__ int   g_cur[NN];
__device__ int   g_csr[EE];
__device__ int   g_bsum[NB];
__device__ int   g_bpre[NB];
__device__ float g_agg[(size_t)NN * DD];          // 25.6 MB
__device__ float g_jk[(size_t)NN * JKD];          // 76.8 MB
__device__ int   g_is64;

// ---------------- f32x2 packed helpers ----------------
__device__ __forceinline__ void ffma2(unsigned long long& d, unsigned long long a,
                                      unsigned long long b) {
    asm("fma.rn.f32x2 %0, %1, %2, %0;" : "+l"(d) : "l"(a), "l"(b));
}
__device__ __forceinline__ unsigned long long splat2(float v) {
    unsigned long long r;
    asm("mov.b64 %0, {%1, %1};" : "=l"(r) : "f"(v));
    return r;
}
__device__ __forceinline__ float2 unpack2(unsigned long long p) {
    float2 r;
    asm("mov.b64 {%0, %1}, %2;" : "=f"(r.x), "=f"(r.y) : "l"(p));
    return r;
}

// ---------------- edge-index dtype detection ----------------
__global__ void detect_kernel(const int* __restrict__ ei32) {
    if (threadIdx.x == 0 && blockIdx.x == 0) {
        int nz = 0;
        for (int i = 1; i < 64; i += 2) nz |= ei32[i];
        g_is64 = (nz == 0) ? 1 : 0;
    }
}

__device__ __forceinline__ void load_edge(const void* ei, int e, int& src, int& dst) {
    if (g_is64) {
        const long long* p = (const long long*)ei;
        src = (int)p[e];
        dst = (int)p[EE + e];
    } else {
        const int* p = (const int*)ei;
        src = p[e];
        dst = p[EE + e];
    }
}

// ---------------- CSR build ----------------
__global__ void zero_deg_kernel() {
    int i = blockIdx.x * blockDim.x + threadIdx.x;
    if (i < NN) g_deg[i] = 0;
}

__global__ void deg_kernel(const void* __restrict__ ei) {
    int e = blockIdx.x * blockDim.x + threadIdx.x;
    if (e < EE) {
        int src, dst;
        load_edge(ei, e, src, dst);
        atomicAdd(&g_deg[dst], 1);
    }
}

__global__ void bsum_kernel() {
    __shared__ int s[256];
    int t = threadIdx.x;
    int i = blockIdx.x * 256 + t;
    s[t] = (i < NN) ? g_deg[i] : 0;
    __syncthreads();
    for (int d = 128; d > 0; d >>= 1) {
        if (t < d) s[t] += s[t + d];
        __syncthreads();
    }
    if (t == 0) g_bsum[blockIdx.x] = s[0];
}

__global__ void bscan_kernel() {
    __shared__ int s[256];
    int t = threadIdx.x;
    int v = (t < NB) ? g_bsum[t] : 0;
    s[t] = v;
    __syncthreads();
    for (int d = 1; d < 256; d <<= 1) {
        int u = (t >= d) ? s[t - d] : 0;
        __syncthreads();
        s[t] += u;
        __syncthreads();
    }
    if (t < NB) g_bpre[t] = s[t] - v;
    if (t == 255) g_off[NN] = s[255];
}

__global__ void offs_kernel() {
    __shared__ int s[256];
    int t = threadIdx.x;
    int i = blockIdx.x * 256 + t;
    int v = (i < NN) ? g_deg[i] : 0;
    s[t] = v;
    __syncthreads();
    for (int d = 1; d < 256; d <<= 1) {
        int u = (t >= d) ? s[t - d] : 0;
        __syncthreads();
        s[t] += u;
        __syncthreads();
    }
    if (i < NN) {
        int excl = s[t] - v + g_bpre[blockIdx.x];
        g_off[i] = excl;
        g_cur[i] = excl;
    }
}

__global__ void fill_kernel(const void* __restrict__ ei) {
    int e = blockIdx.x * blockDim.x + threadIdx.x;
    if (e < EE) {
        int src, dst;
        load_edge(ei, e, src, dst);
        int pos = atomicAdd(&g_cur[dst], 1);
        g_csr[pos] = src;
    }
}

// ---------------- mean aggregation: warp per node, atomic-free ----------------
__global__ void agg_kernel(const float* __restrict__ x, int layer) {
    int warp = (blockIdx.x * blockDim.x + threadIdx.x) >> 5;
    int lane = threadIdx.x & 31;
    if (warp >= NN) return;
    const float* in;
    int stride;
    if (layer == 0) { in = x; stride = DD; }
    else            { in = g_jk + (layer - 1) * DD; stride = JKD; }

    int node = warp;
    int beg = g_off[node], end = g_off[node + 1];
    float4 acc = make_float4(0.f, 0.f, 0.f, 0.f);
    for (int e = beg; e < end; e += 32) {
        int m = min(32, end - e);
        int srcn = (lane < m) ? g_csr[e + lane] : 0;
        for (int i = 0; i < m; i++) {
            int s = __shfl_sync(0xffffffffu, srcn, i);
            const float4 v = *reinterpret_cast<const float4*>(in + (size_t)s * stride + lane * 4);
            acc.x += v.x; acc.y += v.y; acc.z += v.z; acc.w += v.w;
        }
    }
    int deg = end - beg;
    float inv = 1.0f / (float)max(deg, 1);
    float4 o = make_float4(acc.x * inv, acc.y * inv, acc.z * inv, acc.w * inv);
    *reinterpret_cast<float4*>(&g_agg[(size_t)node * DD + lane * 4]) = o;
}

// ---------------- fused layer GEMM (f32x2, conflict-free strips) ----------------
// 256 threads. Tile: 128 nodes x 128 cols. thread: ng=tid>>3 (4 nodes), cg=tid&7.
// cols: 4 strips, strip j covers col j*32 + cg*4 .. +3  (weight LDS.128 contiguous
// 128B across the 8 cg values -> conflict-free).
// K=256 as 2 chunks of 128 (agg | h). Both W chunks resident in smem; Is reused.
#define ISTR 132
__global__ __launch_bounds__(256, 1)
void layer_kernel(const float* __restrict__ x, int layer,
                  const float* __restrict__ Wl, const float* __restrict__ bl,
                  const float* __restrict__ Wr, const float* __restrict__ gamma,
                  const float* __restrict__ beta, const float* __restrict__ rmean,
                  const float* __restrict__ rvar) {
    extern __shared__ float sm[];
    float* Ws = sm;                 // [2][128][128] = 32768 floats (128 KB)
    float* Is = sm + 32768;         // [128][ISTR]   (67.5 KB), reused per chunk

    const float* in;
    int stride;
    if (layer == 0) { in = x; stride = DD; }
    else            { in = g_jk + (layer - 1) * DD; stride = JKD; }

    int tid = threadIdx.x;
    int tileBase = blockIdx.x * 128;

    const float* WlL = Wl + (size_t)layer * DD * DD;
    const float* WrL = Wr + (size_t)layer * DD * DD;

    // load both weight chunks (once)
    for (int idx = tid; idx < 4096; idx += 256) {
        *reinterpret_cast<float4*>(Ws + (size_t)idx * 4) =
            *reinterpret_cast<const float4*>(WlL + (size_t)idx * 4);
        *reinterpret_cast<float4*>(Ws + 16384 + (size_t)idx * 4) =
            *reinterpret_cast<const float4*>(WrL + (size_t)idx * 4);
    }

    int ng = tid >> 3, cg = tid & 7;
    unsigned long long acc[4][4][2];
#pragma unroll
    for (int n = 0; n < 4; n++)
#pragma unroll
        for (int j = 0; j < 4; j++) { acc[n][j][0] = 0ull; acc[n][j][1] = 0ull; }

    for (int chunk = 0; chunk < 2; chunk++) {
        __syncthreads();   // Is free (prior compute done) / weights in flight (chunk0)
        // load Is: 128 rows x 32 float4
        for (int idx = tid; idx < 128 * 32; idx += 256) {
            int m = idx >> 5, k4 = idx & 31;
            int node = tileBase + m;
            float4 v = make_float4(0.f, 0.f, 0.f, 0.f);
            if (node < NN) {
                if (chunk == 0) v = *reinterpret_cast<const float4*>(g_agg + (size_t)node * DD + k4 * 4);
                else            v = *reinterpret_cast<const float4*>(in + (size_t)node * stride + k4 * 4);
            }
            *reinterpret_cast<float4*>(Is + (size_t)m * ISTR + k4 * 4) = v;
        }
        __syncthreads();

        const float* vbase = Is + (size_t)(ng * 4) * ISTR;
        const float* wbase = Ws + (size_t)chunk * 16384 + cg * 4;
#pragma unroll 4
        for (int k = 0; k < 128; k++) {
            ulonglong2 w[4];
#pragma unroll
            for (int j = 0; j < 4; j++)
                w[j] = *reinterpret_cast<const ulonglong2*>(wbase + (size_t)k * 128 + j * 32);
#pragma unroll
            for (int n = 0; n < 4; n++) {
                unsigned long long vv = splat2(vbase[(size_t)n * ISTR + k]);
#pragma unroll
                for (int j = 0; j < 4; j++) {
                    ffma2(acc[n][j][0], vv, w[j].x);
                    ffma2(acc[n][j][1], vv, w[j].y);
                }
            }
        }
    }

    // epilogue: bias + BN folded affine + ReLU, write JK slice
#pragma unroll
    for (int j = 0; j < 4; j++) {
        int c0 = j * 32 + cg * 4;
        float sc[4], sh[4];
#pragma unroll
        for (int c = 0; c < 4; c++) {
            int jj = layer * DD + c0 + c;
            float s = gamma[jj] * rsqrtf(rvar[jj] + 1e-5f);
            sc[c] = s;
            sh[c] = (bl[jj] - rmean[jj]) * s + beta[jj];
        }
#pragma unroll
        for (int n = 0; n < 4; n++) {
            int node = tileBase + ng * 4 + n;
            if (node < NN) {
                float2 u0 = unpack2(acc[n][j][0]);
                float2 u1 = unpack2(acc[n][j][1]);
                float4 r;
                r.x = fmaxf(u0.x * sc[0] + sh[0], 0.f);
                r.y = fmaxf(u0.y * sc[1] + sh[1], 0.f);
                r.z = fmaxf(u1.x * sc[2] + sh[2], 0.f);
                r.w = fmaxf(u1.y * sc[3] + sh[3], 0.f);
                *reinterpret_cast<float4*>(g_jk + (size_t)node * JKD + layer * DD + c0) = r;
            }
        }
    }
}

// ---------------- classifier: 64 nodes / block ----------------
// stage1: thread g=tid>>2 (node), tg=tid&3; 4 strips j: cols j*16 + tg*4 .. +3.
#define JSTR 388
#define ZSTR 68
__global__ __launch_bounds__(256, 1)
void cls_kernel(const float* __restrict__ Wc1, const float* __restrict__ bc1,
                const float* __restrict__ Wc2, const float* __restrict__ bc2,
                float* __restrict__ out) {
    extern __shared__ float sm[];
    float* W1s = sm;                         // 384*64 = 24576 (96 KB)
    float* Js  = sm + 24576;                 // 64*388
    float* Zs  = sm + 24576 + 64 * JSTR;     // 64*68

    int tid = threadIdx.x;
    int nodeBase = blockIdx.x * 64;

    for (int idx = tid; idx < 6144; idx += 256)
        *reinterpret_cast<float4*>(W1s + (size_t)idx * 4) =
            *reinterpret_cast<const float4*>(Wc1 + (size_t)idx * 4);

    for (int idx = tid; idx < 64 * 96; idx += 256) {
        int m = idx / 96, k4 = idx % 96;
        int node = nodeBase + m;
        float4 v = make_float4(0.f, 0.f, 0.f, 0.f);
        if (node < NN) v = *reinterpret_cast<const float4*>(g_jk + (size_t)node * JKD + k4 * 4);
        *reinterpret_cast<float4*>(Js + (size_t)m * JSTR + k4 * 4) = v;
    }
    __syncthreads();

    int g = tid >> 2, tg = tid & 3;
    unsigned long long acc[4][2];
#pragma unroll
    for (int j = 0; j < 4; j++) { acc[j][0] = 0ull; acc[j][1] = 0ull; }

    const float* jrow = Js + (size_t)g * JSTR;
    const float* wp = W1s + tg * 4;
#pragma unroll 4
    for (int k = 0; k < JKD; k++) {
        unsigned long long vv = splat2(jrow[k]);
#pragma unroll
        for (int j = 0; j < 4; j++) {
            ulonglong2 w2 = *reinterpret_cast<const ulonglong2*>(wp + (size_t)k * 64 + j * 16);
            ffma2(acc[j][0], vv, w2.x);
            ffma2(acc[j][1], vv, w2.y);
        }
    }
#pragma unroll
    for (int j = 0; j < 4; j++) {
        int c0 = j * 16 + tg * 4;
        float2 u0 = unpack2(acc[j][0]);
        float2 u1 = unpack2(acc[j][1]);
        float4 b = *reinterpret_cast<const float4*>(bc1 + c0);
        Zs[g * ZSTR + c0 + 0] = fmaxf(u0.x + b.x, 0.f);
        Zs[g * ZSTR + c0 + 1] = fmaxf(u0.y + b.y, 0.f);
        Zs[g * ZSTR + c0 + 2] = fmaxf(u1.x + b.z, 0.f);
        Zs[g * ZSTR + c0 + 3] = fmaxf(u1.y + b.w, 0.f);
    }
    __syncthreads();

    if (tid < 128) {
        int m = tid >> 1, oc = tid & 1;
        int node = nodeBase + m;
        if (node < NN) {
            float sum = bc2[oc];
            const float* zrow = Zs + (size_t)m * ZSTR;
#pragma unroll
            for (int j = 0; j < 64; j++) sum += zrow[j] * Wc2[j * 2 + oc];
            out[(size_t)node * 2 + oc] = sum;
        }
    }
}

// ---------------- host ----------------
extern "C" void kernel_launch(void* const* d_in, const int* in_sizes, int n_in,
                              void* d_out, int out_size) {
    const float* x     = (const float*)d_in[0];
    const void*  ei    = d_in[1];
    const float* Wl    = (const float*)d_in[2];
    const float* bl    = (const float*)d_in[3];
    const float* Wr    = (const float*)d_in[4];
    const float* gamma = (const float*)d_in[5];
    const float* beta  = (const float*)d_in[6];
    const float* rmean = (const float*)d_in[7];
    const float* rvar  = (const float*)d_in[8];
    const float* Wc1   = (const float*)d_in[9];
    const float* bc1   = (const float*)d_in[10];
    const float* Wc2   = (const float*)d_in[11];
    const float* bc2   = (const float*)d_in[12];
    float* out = (float*)d_out;

    // smem: layer = (32768 + 128*132)*4 = 198656 B ; cls = (24576+64*388+64*68)*4 = 215040 B
    cudaFuncSetAttribute(layer_kernel, cudaFuncAttributeMaxDynamicSharedMemorySize, 198656);
    cudaFuncSetAttribute(cls_kernel,   cudaFuncAttributeMaxDynamicSharedMemorySize, 215040);

    detect_kernel<<<1, 32>>>((const int*)ei);
    zero_deg_kernel<<<(NN + 255) / 256, 256>>>();
    deg_kernel<<<(EE + 255) / 256, 256>>>(ei);
    bsum_kernel<<<NB, 256>>>();
    bscan_kernel<<<1, 256>>>();
    offs_kernel<<<NB, 256>>>();
    fill_kernel<<<(EE + 255) / 256, 256>>>(ei);

    for (int layer = 0; layer < LL; layer++) {
        agg_kernel<<<(NN * 32 + 255) / 256, 256>>>(x, layer);
        layer_kernel<<<(NN + 127) / 128, 256, 198656>>>(x, layer, Wl, bl, Wr,
                                                        gamma, beta, rmean, rvar);
    }
    cls_kernel<<<(NN + 63) / 64, 256, 215040>>>(Wc1, bc1, Wc2, bc2, out);
}

// round 6
// speedup vs baseline: 1.6600x; 1.2275x over previous
#include <cuda_runtime.h>
#include <cuda_bf16.h>
#include <cstdint>

#define NN 50000
#define EE 800000
#define DD 128
#define LL 3
#define JKD (LL*DD)   // 384
#define H2 64
#define NB 196        // ceil(NN/256)

// ---------------- scratch (device globals) ----------------
__device__ int   g_deg[NN];
__device__ int   g_off[NN + 1];
__device__ int   g_cur[NN];
__device__ int   g_csr[EE];
__device__ int   g_bsum[NB];
__device__ int   g_bpre[NB];
__device__ float g_agg[(size_t)NN * DD];
__device__ float g_jk[(size_t)NN * JKD];
__device__ int   g_is64;
// weights: [layer][mat(l/r)][split(hi/lo)][n][k] bf16 (transposed to [n][k])
__device__ __nv_bfloat16 g_Wb[LL * 2 * 2 * DD * DD];

// ---------------- f32x2 helpers (classifier) ----------------
__device__ __forceinline__ void ffma2(unsigned long long& d, unsigned long long a,
                                      unsigned long long b) {
    asm("fma.rn.f32x2 %0, %1, %2, %0;" : "+l"(d) : "l"(a), "l"(b));
}
__device__ __forceinline__ unsigned long long splat2(float v) {
    unsigned long long r;
    asm("mov.b64 %0, {%1, %1};" : "=l"(r) : "f"(v));
    return r;
}
__device__ __forceinline__ float2 unpack2(unsigned long long p) {
    float2 r;
    asm("mov.b64 {%0, %1}, %2;" : "=f"(r.x), "=f"(r.y) : "l"(p));
    return r;
}

// ---------------- mma.sync bf16 (sm_80 PTX -> works on compute_103) ----------------
__device__ __forceinline__ void mma16816(float* c, const uint32_t* a, const uint32_t* b) {
    asm volatile("mma.sync.aligned.m16n8k16.row.col.f32.bf16.bf16.f32 "
        "{%0,%1,%2,%3}, {%4,%5,%6,%7}, {%8,%9}, {%0,%1,%2,%3};"
        : "+f"(c[0]), "+f"(c[1]), "+f"(c[2]), "+f"(c[3])
        : "r"(a[0]), "r"(a[1]), "r"(a[2]), "r"(a[3]), "r"(b[0]), "r"(b[1]));
}

// ---------------- edge-index dtype detection ----------------
__global__ void detect_kernel(const int* __restrict__ ei32) {
    if (threadIdx.x == 0 && blockIdx.x == 0) {
        int nz = 0;
        for (int i = 1; i < 64; i += 2) nz |= ei32[i];
        g_is64 = (nz == 0) ? 1 : 0;
    }
}

__device__ __forceinline__ void load_edge(const void* ei, int e, int& src, int& dst) {
    if (g_is64) {
        const long long* p = (const long long*)ei;
        src = (int)p[e];
        dst = (int)p[EE + e];
    } else {
        const int* p = (const int*)ei;
        src = p[e];
        dst = p[EE + e];
    }
}

// ---------------- weight prep: transpose + bf16 hi/lo split ----------------
__global__ void wprep_kernel(const float* __restrict__ Wl, const float* __restrict__ Wr) {
    int i = blockIdx.x * blockDim.x + threadIdx.x;   // [layer][mat][n][k]
    if (i >= LL * 2 * DD * DD) return;
    int k = i & 127, n = (i >> 7) & 127, mat = (i >> 14) & 1, layer = i >> 15;
    const float* W = mat ? Wr : Wl;
    float w = W[(size_t)layer * DD * DD + (size_t)k * DD + n];   // transpose
    __nv_bfloat16 h = __float2bfloat16_rn(w);
    __nv_bfloat16 l = __float2bfloat16_rn(w - __bfloat162float(h));
    size_t base = (size_t)((layer * 2 + mat) * 2) * DD * DD + (size_t)n * DD + k;
    g_Wb[base] = h;
    g_Wb[base + (size_t)DD * DD] = l;
}

// ---------------- CSR build ----------------
__global__ void zero_deg_kernel() {
    int i = blockIdx.x * blockDim.x + threadIdx.x;
    if (i < NN) g_deg[i] = 0;
}
__global__ void deg_kernel(const void* __restrict__ ei) {
    int e = blockIdx.x * blockDim.x + threadIdx.x;
    if (e < EE) {
        int src, dst;
        load_edge(ei, e, src, dst);
        atomicAdd(&g_deg[dst], 1);
    }
}
__global__ void bsum_kernel() {
    __shared__ int s[256];
    int t = threadIdx.x;
    int i = blockIdx.x * 256 + t;
    s[t] = (i < NN) ? g_deg[i] : 0;
    __syncthreads();
    for (int d = 128; d > 0; d >>= 1) {
        if (t < d) s[t] += s[t + d];
        __syncthreads();
    }
    if (t == 0) g_bsum[blockIdx.x] = s[0];
}
__global__ void bscan_kernel() {
    __shared__ int s[256];
    int t = threadIdx.x;
    int v = (t < NB) ? g_bsum[t] : 0;
    s[t] = v;
    __syncthreads();
    for (int d = 1; d < 256; d <<= 1) {
        int u = (t >= d) ? s[t - d] : 0;
        __syncthreads();
        s[t] += u;
        __syncthreads();
    }
    if (t < NB) g_bpre[t] = s[t] - v;
    if (t == 255) g_off[NN] = s[255];
}
__global__ void offs_kernel() {
    __shared__ int s[256];
    int t = threadIdx.x;
    int i = blockIdx.x * 256 + t;
    int v = (i < NN) ? g_deg[i] : 0;
    s[t] = v;
    __syncthreads();
    for (int d = 1; d < 256; d <<= 1) {
        int u = (t >= d) ? s[t - d] : 0;
        __syncthreads();
        s[t] += u;
        __syncthreads();
    }
    if (i < NN) {
        int excl = s[t] - v + g_bpre[blockIdx.x];
        g_off[i] = excl;
        g_cur[i] = excl;
    }
}
__global__ void fill_kernel(const void* __restrict__ ei) {
    int e = blockIdx.x * blockDim.x + threadIdx.x;
    if (e < EE) {
        int src, dst;
        load_edge(ei, e, src, dst);
        int pos = atomicAdd(&g_cur[dst], 1);
        g_csr[pos] = src;
    }
}

// ---------------- mean aggregation ----------------
__global__ void agg_kernel(const float* __restrict__ x, int layer) {
    int warp = (blockIdx.x * blockDim.x + threadIdx.x) >> 5;
    int lane = threadIdx.x & 31;
    if (warp >= NN) return;
    const float* in;
    int stride;
    if (layer == 0) { in = x; stride = DD; }
    else            { in = g_jk + (layer - 1) * DD; stride = JKD; }

    int node = warp;
    int beg = g_off[node], end = g_off[node + 1];
    float4 acc = make_float4(0.f, 0.f, 0.f, 0.f);
    for (int e = beg; e < end; e += 32) {
        int m = min(32, end - e);
        int srcn = (lane < m) ? g_csr[e + lane] : 0;
        for (int i = 0; i < m; i++) {
            int s = __shfl_sync(0xffffffffu, srcn, i);
            const float4 v = *reinterpret_cast<const float4*>(in + (size_t)s * stride + lane * 4);
            acc.x += v.x; acc.y += v.y; acc.z += v.z; acc.w += v.w;
        }
    }
    int deg = end - beg;
    float inv = 1.0f / (float)max(deg, 1);
    float4 o = make_float4(acc.x * inv, acc.y * inv, acc.z * inv, acc.w * inv);
    *reinterpret_cast<float4*>(&g_agg[(size_t)node * DD + lane * 4]) = o;
}

// ---------------- layer GEMM via mma.sync bf16 hi/lo split ----------------
// Tile: 128 nodes x 128 cols, K=256 (chunk0 = agg @ Wl, chunk1 = h @ Wr).
// Warps: 2 (rows) x 4 (cols); warp tile 64 x 32; mma m16n8k16.
// A and W rows padded to AST=136 bf16 (272 B) -> all frag loads conflict-free.
#define AST 136
#define TILEB (128 * AST * 2)   // 34816 B per tile
#define SMEM_LAYER_TOTAL (6 * TILEB)   // Ah, Al, 4x W = 208896 B

__global__ __launch_bounds__(256, 1)
void layer_kernel(const float* __restrict__ x, int layer,
                  const float* __restrict__ bl, const float* __restrict__ gamma,
                  const float* __restrict__ beta, const float* __restrict__ rmean,
                  const float* __restrict__ rvar) {
    extern __shared__ char smem[];
    char* Ah = smem;
    char* Al = smem + TILEB;
    char* Ws = smem + 2 * TILEB;   // 4 buffers: [chunk][split]

    int tid = threadIdx.x;
    int warp = tid >> 5, lane = tid & 31;
    int wr = warp >> 2, wc = warp & 3;      // 2 x 4 warp grid
    int g = lane >> 2, t = lane & 3;
    int tileBase = blockIdx.x * 128;

    const float* in;
    int stride;
    if (layer == 0) { in = x; stride = DD; }
    else            { in = g_jk + (layer - 1) * DD; stride = JKD; }

    // load weights: 4 buffers x 128 rows x 16 x uint4
    for (int idx = tid; idx < 4 * 128 * 16; idx += 256) {
        int b = idx >> 11, r = idx & 2047;
        int n = r >> 4, k8 = r & 15;
        const __nv_bfloat16* src = g_Wb +
            (size_t)((layer * 2 + (b >> 1)) * 2 + (b & 1)) * DD * DD + (size_t)n * DD + k8 * 8;
        uint4 v = *reinterpret_cast<const uint4*>(src);
        *reinterpret_cast<uint4*>(Ws + (size_t)b * TILEB + n * 272 + k8 * 16) = v;
    }

    float acc[4][4][4];
#pragma unroll
    for (int rt = 0; rt < 4; rt++)
#pragma unroll
        for (int ct = 0; ct < 4; ct++)
#pragma unroll
            for (int q = 0; q < 4; q++) acc[rt][ct][q] = 0.f;

    for (int chunk = 0; chunk < 2; chunk++) {
        __syncthreads();   // Ws ready (chunk0) / prior compute done (chunk1)
        // convert A chunk -> bf16 hi/lo (row-major, padded stride)
        for (int idx = tid; idx < 128 * 64; idx += 256) {
            int m = idx >> 6, p = idx & 63;      // element pair (2p, 2p+1)
            int node = tileBase + m;
            float2 v = make_float2(0.f, 0.f);
            if (node < NN) {
                if (chunk == 0) v = *reinterpret_cast<const float2*>(g_agg + (size_t)node * DD + 2 * p);
                else            v = *reinterpret_cast<const float2*>(in + (size_t)node * stride + 2 * p);
            }
            __nv_bfloat162 h2 = __float22bfloat162_rn(v);
            float2 hf = __bfloat1622float2(h2);
            __nv_bfloat162 l2 = __float22bfloat162_rn(make_float2(v.x - hf.x, v.y - hf.y));
            *reinterpret_cast<uint32_t*>(Ah + m * 272 + p * 4) = *reinterpret_cast<uint32_t*>(&h2);
            *reinterpret_cast<uint32_t*>(Al + m * 272 + p * 4) = *reinterpret_cast<uint32_t*>(&l2);
        }
        __syncthreads();

#pragma unroll
        for (int s = 0; s < 3; s++) {
            const char* A = (s == 2) ? Al : Ah;
            const char* W = Ws + (size_t)(chunk * 2 + (s == 1 ? 1 : 0)) * TILEB;
#pragma unroll
            for (int k16 = 0; k16 < 8; k16++) {
                int kb = k16 * 32 + t * 4;   // byte offset of element 2t in this k-group
                uint32_t a[4][4], bb[4][2];
#pragma unroll
                for (int rt = 0; rt < 4; rt++) {
                    const char* base = A + (size_t)(wr * 64 + rt * 16 + g) * 272 + kb;
                    a[rt][0] = *reinterpret_cast<const uint32_t*>(base);
                    a[rt][1] = *reinterpret_cast<const uint32_t*>(base + 8 * 272);
                    a[rt][2] = *reinterpret_cast<const uint32_t*>(base + 16);
                    a[rt][3] = *reinterpret_cast<const uint32_t*>(base + 8 * 272 + 16);
                }
#pragma unroll
                for (int ct = 0; ct < 4; ct++) {
                    const char* base = W + (size_t)(wc * 32 + ct * 8 + g) * 272 + kb;
                    bb[ct][0] = *reinterpret_cast<const uint32_t*>(base);
                    bb[ct][1] = *reinterpret_cast<const uint32_t*>(base + 16);
                }
#pragma unroll
                for (int rt = 0; rt < 4; rt++)
#pragma unroll
                    for (int ct = 0; ct < 4; ct++)
                        mma16816(acc[rt][ct], a[rt], bb[ct]);
            }
        }
    }

    // epilogue: per-column affine (bias+BN) + ReLU, float2 stores
    float2 scv[4], shv[4];
#pragma unroll
    for (int ct = 0; ct < 4; ct++) {
        int j = layer * DD + wc * 32 + ct * 8 + 2 * t;
        float s0 = gamma[j] * rsqrtf(rvar[j] + 1e-5f);
        float s1 = gamma[j + 1] * rsqrtf(rvar[j + 1] + 1e-5f);
        scv[ct] = make_float2(s0, s1);
        shv[ct] = make_float2((bl[j] - rmean[j]) * s0 + beta[j],
                              (bl[j + 1] - rmean[j + 1]) * s1 + beta[j + 1]);
    }
#pragma unroll
    for (int rt = 0; rt < 4; rt++) {
        int row0 = tileBase + wr * 64 + rt * 16 + g;
        int row1 = row0 + 8;
#pragma unroll
        for (int ct = 0; ct < 4; ct++) {
            int coff = layer * DD + wc * 32 + ct * 8 + 2 * t;
            if (row0 < NN) {
                float2 o;
                o.x = fmaxf(acc[rt][ct][0] * scv[ct].x + shv[ct].x, 0.f);
                o.y = fmaxf(acc[rt][ct][1] * scv[ct].y + shv[ct].y, 0.f);
                *reinterpret_cast<float2*>(g_jk + (size_t)row0 * JKD + coff) = o;
            }
            if (row1 < NN) {
                float2 o;
                o.x = fmaxf(acc[rt][ct][2] * scv[ct].x + shv[ct].x, 0.f);
                o.y = fmaxf(acc[rt][ct][3] * scv[ct].y + shv[ct].y, 0.f);
                *reinterpret_cast<float2*>(g_jk + (size_t)row1 * JKD + coff) = o;
            }
        }
    }
}

// ---------------- classifier (f32x2, 64 nodes/block) ----------------
#define JSTR 388
#define ZSTR 68
__global__ __launch_bounds__(256, 1)
void cls_kernel(const float* __restrict__ Wc1, const float* __restrict__ bc1,
                const float* __restrict__ Wc2, const float* __restrict__ bc2,
                float* __restrict__ out) {
    extern __shared__ float sm[];
    float* W1s = sm;
    float* Js  = sm + 24576;
    float* Zs  = sm + 24576 + 64 * JSTR;

    int tid = threadIdx.x;
    int nodeBase = blockIdx.x * 64;

    for (int idx = tid; idx < 6144; idx += 256)
        *reinterpret_cast<float4*>(W1s + (size_t)idx * 4) =
            *reinterpret_cast<const float4*>(Wc1 + (size_t)idx * 4);

    for (int idx = tid; idx < 64 * 96; idx += 256) {
        int m = idx / 96, k4 = idx % 96;
        int node = nodeBase + m;
        float4 v = make_float4(0.f, 0.f, 0.f, 0.f);
        if (node < NN) v = *reinterpret_cast<const float4*>(g_jk + (size_t)node * JKD + k4 * 4);
        *reinterpret_cast<float4*>(Js + (size_t)m * JSTR + k4 * 4) = v;
    }
    __syncthreads();

    int g = tid >> 2, tg = tid & 3;
    unsigned long long acc[4][2];
#pragma unroll
    for (int j = 0; j < 4; j++) { acc[j][0] = 0ull; acc[j][1] = 0ull; }

    const float* jrow = Js + (size_t)g * JSTR;
    const float* wp = W1s + tg * 4;
#pragma unroll 4
    for (int k = 0; k < JKD; k++) {
        unsigned long long vv = splat2(jrow[k]);
#pragma unroll
        for (int j = 0; j < 4; j++) {
            ulonglong2 w2 = *reinterpret_cast<const ulonglong2*>(wp + (size_t)k * 64 + j * 16);
            ffma2(acc[j][0], vv, w2.x);
            ffma2(acc[j][1], vv, w2.y);
        }
    }
#pragma unroll
    for (int j = 0; j < 4; j++) {
        int c0 = j * 16 + tg * 4;
        float2 u0 = unpack2(acc[j][0]);
        float2 u1 = unpack2(acc[j][1]);
        float4 b = *reinterpret_cast<const float4*>(bc1 + c0);
        Zs[g * ZSTR + c0 + 0] = fmaxf(u0.x + b.x, 0.f);
        Zs[g * ZSTR + c0 + 1] = fmaxf(u0.y + b.y, 0.f);
        Zs[g * ZSTR + c0 + 2] = fmaxf(u1.x + b.z, 0.f);
        Zs[g * ZSTR + c0 + 3] = fmaxf(u1.y + b.w, 0.f);
    }
    __syncthreads();

    if (tid < 128) {
        int m = tid >> 1, oc = tid & 1;
        int node = nodeBase + m;
        if (node < NN) {
            float sum = bc2[oc];
            const float* zrow = Zs + (size_t)m * ZSTR;
#pragma unroll
            for (int j = 0; j < 64; j++) sum += zrow[j] * Wc2[j * 2 + oc];
            out[(size_t)node * 2 + oc] = sum;
        }
    }
}

// ---------------- host ----------------
extern "C" void kernel_launch(void* const* d_in, const int* in_sizes, int n_in,
                              void* d_out, int out_size) {
    const float* x     = (const float*)d_in[0];
    const void*  ei    = d_in[1];
    const float* Wl    = (const float*)d_in[2];
    const float* bl    = (const float*)d_in[3];
    const float* Wr    = (const float*)d_in[4];
    const float* gamma = (const float*)d_in[5];
    const float* beta  = (const float*)d_in[6];
    const float* rmean = (const float*)d_in[7];
    const float* rvar  = (const float*)d_in[8];
    const float* Wc1   = (const float*)d_in[9];
    const float* bc1   = (const float*)d_in[10];
    const float* Wc2   = (const float*)d_in[11];
    const float* bc2   = (const float*)d_in[12];
    float* out = (float*)d_out;

    cudaFuncSetAttribute(layer_kernel, cudaFuncAttributeMaxDynamicSharedMemorySize, SMEM_LAYER_TOTAL);
    cudaFuncSetAttribute(cls_kernel,   cudaFuncAttributeMaxDynamicSharedMemorySize, 215040);

    detect_kernel<<<1, 32>>>((const int*)ei);
    wprep_kernel<<<(LL * 2 * DD * DD + 255) / 256, 256>>>(Wl, Wr);
    zero_deg_kernel<<<(NN + 255) / 256, 256>>>();
    deg_kernel<<<(EE + 255) / 256, 256>>>(ei);
    bsum_kernel<<<NB, 256>>>();
    bscan_kernel<<<1, 256>>>();
    offs_kernel<<<NB, 256>>>();
    fill_kernel<<<(EE + 255) / 256, 256>>>(ei);

    for (int layer = 0; layer < LL; layer++) {
        agg_kernel<<<(NN * 32 + 255) / 256, 256>>>(x, layer);
        layer_kernel<<<(NN + 127) / 128, 256, SMEM_LAYER_TOTAL>>>(x, layer, bl,
                                                                  gamma, beta, rmean, rvar);
    }
    cls_kernel<<<(NN + 63) / 64, 256, 215040>>>(Wc1, bc1, Wc2, bc2, out);
}

// round 7
// speedup vs baseline: 2.0974x; 1.2635x over previous
#include <cuda_runtime.h>
#include <cuda_bf16.h>
#include <cstdint>

#define NN 50000
#define EE 800000
#define DD 128
#define LL 3
#define JKD (LL*DD)   // 384
#define H2 64
#define NB 196        // ceil(NN/256)

// ---------------- scratch (device globals) ----------------
__device__ int   g_deg[NN];
__device__ int   g_off[NN + 1];
__device__ int   g_cur[NN];
__device__ int   g_csr[EE];
__device__ int   g_bsum[NB];
__device__ int   g_bpre[NB];
__device__ float g_agg[(size_t)NN * DD];
__device__ float g_jk[(size_t)NN * JKD];
__device__ int   g_is64;
// layer weights: [layer][mat(l/r)][split(hi/lo)][n][k] bf16 (transposed)
__device__ __nv_bfloat16 g_Wb[LL * 2 * 2 * DD * DD];
// classifier W1: [split(hi/lo)][n(64)][k(384)] bf16 (transposed)
__device__ __nv_bfloat16 g_W1b[2 * H2 * JKD];

// ---------------- mma.sync bf16 ----------------
__device__ __forceinline__ void mma16816(float* c, const uint32_t* a, const uint32_t* b) {
    asm volatile("mma.sync.aligned.m16n8k16.row.col.f32.bf16.bf16.f32 "
        "{%0,%1,%2,%3}, {%4,%5,%6,%7}, {%8,%9}, {%0,%1,%2,%3};"
        : "+f"(c[0]), "+f"(c[1]), "+f"(c[2]), "+f"(c[3])
        : "r"(a[0]), "r"(a[1]), "r"(a[2]), "r"(a[3]), "r"(b[0]), "r"(b[1]));
}

// ---------------- edge-index dtype detection ----------------
__global__ void detect_kernel(const int* __restrict__ ei32) {
    if (threadIdx.x == 0 && blockIdx.x == 0) {
        int nz = 0;
        for (int i = 1; i < 64; i += 2) nz |= ei32[i];
        g_is64 = (nz == 0) ? 1 : 0;
    }
}

__device__ __forceinline__ void load_edge(const void* ei, int e, int& src, int& dst) {
    if (g_is64) {
        const long long* p = (const long long*)ei;
        src = (int)p[e];
        dst = (int)p[EE + e];
    } else {
        const int* p = (const int*)ei;
        src = p[e];
        dst = p[EE + e];
    }
}

// ---------------- weight prep ----------------
__global__ void wprep_kernel(const float* __restrict__ Wl, const float* __restrict__ Wr) {
    int i = blockIdx.x * blockDim.x + threadIdx.x;
    if (i >= LL * 2 * DD * DD) return;
    int k = i & 127, n = (i >> 7) & 127, mat = (i >> 14) & 1, layer = i >> 15;
    const float* W = mat ? Wr : Wl;
    float w = W[(size_t)layer * DD * DD + (size_t)k * DD + n];
    __nv_bfloat16 h = __float2bfloat16_rn(w);
    __nv_bfloat16 l = __float2bfloat16_rn(w - __bfloat162float(h));
    size_t base = (size_t)((layer * 2 + mat) * 2) * DD * DD + (size_t)n * DD + k;
    g_Wb[base] = h;
    g_Wb[base + (size_t)DD * DD] = l;
}

__global__ void wprep2_kernel(const float* __restrict__ Wc1) {
    int i = blockIdx.x * blockDim.x + threadIdx.x;
    if (i >= H2 * JKD) return;
    int k = i % JKD, n = i / JKD;
    float w = Wc1[(size_t)k * H2 + n];
    __nv_bfloat16 h = __float2bfloat16_rn(w);
    __nv_bfloat16 l = __float2bfloat16_rn(w - __bfloat162float(h));
    g_W1b[(size_t)n * JKD + k] = h;
    g_W1b[(size_t)H2 * JKD + (size_t)n * JKD + k] = l;
}

// ---------------- CSR build ----------------
__global__ void zero_deg_kernel() {
    int i = blockIdx.x * blockDim.x + threadIdx.x;
    if (i < NN) g_deg[i] = 0;
}
__global__ void deg_kernel(const void* __restrict__ ei) {
    int e = blockIdx.x * blockDim.x + threadIdx.x;
    if (e < EE) {
        int src, dst;
        load_edge(ei, e, src, dst);
        atomicAdd(&g_deg[dst], 1);
    }
}
__global__ void bsum_kernel() {
    __shared__ int s[256];
    int t = threadIdx.x;
    int i = blockIdx.x * 256 + t;
    s[t] = (i < NN) ? g_deg[i] : 0;
    __syncthreads();
    for (int d = 128; d > 0; d >>= 1) {
        if (t < d) s[t] += s[t + d];
        __syncthreads();
    }
    if (t == 0) g_bsum[blockIdx.x] = s[0];
}
__global__ void bscan_kernel() {
    __shared__ int s[256];
    int t = threadIdx.x;
    int v = (t < NB) ? g_bsum[t] : 0;
    s[t] = v;
    __syncthreads();
    for (int d = 1; d < 256; d <<= 1) {
        int u = (t >= d) ? s[t - d] : 0;
        __syncthreads();
        s[t] += u;
        __syncthreads();
    }
    if (t < NB) g_bpre[t] = s[t] - v;
    if (t == 255) g_off[NN] = s[255];
}
__global__ void offs_kernel() {
    __shared__ int s[256];
    int t = threadIdx.x;
    int i = blockIdx.x * 256 + t;
    int v = (i < NN) ? g_deg[i] : 0;
    s[t] = v;
    __syncthreads();
    for (int d = 1; d < 256; d <<= 1) {
        int u = (t >= d) ? s[t - d] : 0;
        __syncthreads();
        s[t] += u;
        __syncthreads();
    }
    if (i < NN) {
        int excl = s[t] - v + g_bpre[blockIdx.x];
        g_off[i] = excl;
        g_cur[i] = excl;
    }
}
__global__ void fill_kernel(const void* __restrict__ ei) {
    int e = blockIdx.x * blockDim.x + threadIdx.x;
    if (e < EE) {
        int src, dst;
        load_edge(ei, e, src, dst);
        int pos = atomicAdd(&g_cur[dst], 1);
        g_csr[pos] = src;
    }
}

// ---------------- mean aggregation: warp/node, unroll-4 for MLP ----------------
__global__ void agg_kernel(const float* __restrict__ x, int layer) {
    int warp = (blockIdx.x * blockDim.x + threadIdx.x) >> 5;
    int lane = threadIdx.x & 31;
    if (warp >= NN) return;
    const float* in;
    int stride;
    if (layer == 0) { in = x; stride = DD; }
    else            { in = g_jk + (layer - 1) * DD; stride = JKD; }

    int node = warp;
    int beg = g_off[node], end = g_off[node + 1];
    float4 acc0 = make_float4(0.f, 0.f, 0.f, 0.f);
    float4 acc1 = make_float4(0.f, 0.f, 0.f, 0.f);
    for (int e = beg; e < end; e += 32) {
        int m = min(32, end - e);
        int srcn = (lane < m) ? g_csr[e + lane] : 0;
        int i = 0;
        for (; i + 4 <= m; i += 4) {
            int s0 = __shfl_sync(0xffffffffu, srcn, i);
            int s1 = __shfl_sync(0xffffffffu, srcn, i + 1);
            int s2 = __shfl_sync(0xffffffffu, srcn, i + 2);
            int s3 = __shfl_sync(0xffffffffu, srcn, i + 3);
            float4 v0 = *reinterpret_cast<const float4*>(in + (size_t)s0 * stride + lane * 4);
            float4 v1 = *reinterpret_cast<const float4*>(in + (size_t)s1 * stride + lane * 4);
            float4 v2 = *reinterpret_cast<const float4*>(in + (size_t)s2 * stride + lane * 4);
            float4 v3 = *reinterpret_cast<const float4*>(in + (size_t)s3 * stride + lane * 4);
            acc0.x += v0.x; acc0.y += v0.y; acc0.z += v0.z; acc0.w += v0.w;
            acc1.x += v1.x; acc1.y += v1.y; acc1.z += v1.z; acc1.w += v1.w;
            acc0.x += v2.x; acc0.y += v2.y; acc0.z += v2.z; acc0.w += v2.w;
            acc1.x += v3.x; acc1.y += v3.y; acc1.z += v3.z; acc1.w += v3.w;
        }
        for (; i < m; i++) {
            int s = __shfl_sync(0xffffffffu, srcn, i);
            float4 v = *reinterpret_cast<const float4*>(in + (size_t)s * stride + lane * 4);
            acc0.x += v.x; acc0.y += v.y; acc0.z += v.z; acc0.w += v.w;
        }
    }
    int deg = end - beg;
    float inv = 1.0f / (float)max(deg, 1);
    float4 o = make_float4((acc0.x + acc1.x) * inv, (acc0.y + acc1.y) * inv,
                           (acc0.z + acc1.z) * inv, (acc0.w + acc1.w) * inv);
    *reinterpret_cast<float4*>(&g_agg[(size_t)node * DD + lane * 4]) = o;
}

// ---------------- layer GEMM via mma.sync bf16 hi/lo (unchanged from R6) ----------------
#define AST 136
#define TILEB (128 * AST * 2)   // 34816 B per tile
#define SMEM_LAYER_TOTAL (6 * TILEB)   // 208896 B

__global__ __launch_bounds__(256, 1)
void layer_kernel(const float* __restrict__ x, int layer,
                  const float* __restrict__ bl, const float* __restrict__ gamma,
                  const float* __restrict__ beta, const float* __restrict__ rmean,
                  const float* __restrict__ rvar) {
    extern __shared__ char smem[];
    char* Ah = smem;
    char* Al = smem + TILEB;
    char* Ws = smem + 2 * TILEB;

    int tid = threadIdx.x;
    int warp = tid >> 5, lane = tid & 31;
    int wr = warp >> 2, wc = warp & 3;
    int g = lane >> 2, t = lane & 3;
    int tileBase = blockIdx.x * 128;

    const float* in;
    int stride;
    if (layer == 0) { in = x; stride = DD; }
    else            { in = g_jk + (layer - 1) * DD; stride = JKD; }

    for (int idx = tid; idx < 4 * 128 * 16; idx += 256) {
        int b = idx >> 11, r = idx & 2047;
        int n = r >> 4, k8 = r & 15;
        const __nv_bfloat16* src = g_Wb +
            (size_t)((layer * 2 + (b >> 1)) * 2 + (b & 1)) * DD * DD + (size_t)n * DD + k8 * 8;
        uint4 v = *reinterpret_cast<const uint4*>(src);
        *reinterpret_cast<uint4*>(Ws + (size_t)b * TILEB + n * 272 + k8 * 16) = v;
    }

    float acc[4][4][4];
#pragma unroll
    for (int rt = 0; rt < 4; rt++)
#pragma unroll
        for (int ct = 0; ct < 4; ct++)
#pragma unroll
            for (int q = 0; q < 4; q++) acc[rt][ct][q] = 0.f;

    for (int chunk = 0; chunk < 2; chunk++) {
        __syncthreads();
        for (int idx = tid; idx < 128 * 64; idx += 256) {
            int m = idx >> 6, p = idx & 63;
            int node = tileBase + m;
            float2 v = make_float2(0.f, 0.f);
            if (node < NN) {
                if (chunk == 0) v = *reinterpret_cast<const float2*>(g_agg + (size_t)node * DD + 2 * p);
                else            v = *reinterpret_cast<const float2*>(in + (size_t)node * stride + 2 * p);
            }
            __nv_bfloat162 h2 = __float22bfloat162_rn(v);
            float2 hf = __bfloat1622float2(h2);
            __nv_bfloat162 l2 = __float22bfloat162_rn(make_float2(v.x - hf.x, v.y - hf.y));
            *reinterpret_cast<uint32_t*>(Ah + m * 272 + p * 4) = *reinterpret_cast<uint32_t*>(&h2);
            *reinterpret_cast<uint32_t*>(Al + m * 272 + p * 4) = *reinterpret_cast<uint32_t*>(&l2);
        }
        __syncthreads();

#pragma unroll
        for (int s = 0; s < 3; s++) {
            const char* A = (s == 2) ? Al : Ah;
            const char* W = Ws + (size_t)(chunk * 2 + (s == 1 ? 1 : 0)) * TILEB;
#pragma unroll
            for (int k16 = 0; k16 < 8; k16++) {
                int kb = k16 * 32 + t * 4;
                uint32_t a[4][4], bb[4][2];
#pragma unroll
                for (int rt = 0; rt < 4; rt++) {
                    const char* base = A + (size_t)(wr * 64 + rt * 16 + g) * 272 + kb;
                    a[rt][0] = *reinterpret_cast<const uint32_t*>(base);
                    a[rt][1] = *reinterpret_cast<const uint32_t*>(base + 8 * 272);
                    a[rt][2] = *reinterpret_cast<const uint32_t*>(base + 16);
                    a[rt][3] = *reinterpret_cast<const uint32_t*>(base + 8 * 272 + 16);
                }
#pragma unroll
                for (int ct = 0; ct < 4; ct++) {
                    const char* base = W + (size_t)(wc * 32 + ct * 8 + g) * 272 + kb;
                    bb[ct][0] = *reinterpret_cast<const uint32_t*>(base);
                    bb[ct][1] = *reinterpret_cast<const uint32_t*>(base + 16);
                }
#pragma unroll
                for (int rt = 0; rt < 4; rt++)
#pragma unroll
                    for (int ct = 0; ct < 4; ct++)
                        mma16816(acc[rt][ct], a[rt], bb[ct]);
            }
        }
    }

    float2 scv[4], shv[4];
#pragma unroll
    for (int ct = 0; ct < 4; ct++) {
        int j = layer * DD + wc * 32 + ct * 8 + 2 * t;
        float s0 = gamma[j] * rsqrtf(rvar[j] + 1e-5f);
        float s1 = gamma[j + 1] * rsqrtf(rvar[j + 1] + 1e-5f);
        scv[ct] = make_float2(s0, s1);
        shv[ct] = make_float2((bl[j] - rmean[j]) * s0 + beta[j],
                              (bl[j + 1] - rmean[j + 1]) * s1 + beta[j + 1]);
    }
#pragma unroll
    for (int rt = 0; rt < 4; rt++) {
        int row0 = tileBase + wr * 64 + rt * 16 + g;
        int row1 = row0 + 8;
#pragma unroll
        for (int ct = 0; ct < 4; ct++) {
            int coff = layer * DD + wc * 32 + ct * 8 + 2 * t;
            if (row0 < NN) {
                float2 o;
                o.x = fmaxf(acc[rt][ct][0] * scv[ct].x + shv[ct].x, 0.f);
                o.y = fmaxf(acc[rt][ct][1] * scv[ct].y + shv[ct].y, 0.f);
                *reinterpret_cast<float2*>(g_jk + (size_t)row0 * JKD + coff) = o;
            }
            if (row1 < NN) {
                float2 o;
                o.x = fmaxf(acc[rt][ct][2] * scv[ct].x + shv[ct].x, 0.f);
                o.y = fmaxf(acc[rt][ct][3] * scv[ct].y + shv[ct].y, 0.f);
                *reinterpret_cast<float2*>(g_jk + (size_t)row1 * JKD + coff) = o;
            }
        }
    }
}

// ---------------- classifier: stage1 on tensor cores (bf16 hi/lo) ----------------
// M tile 64 nodes, N=64, K=384. Warps 4 (rows) x 2 (cols); warp tile 16 x 32.
// smem stride 392 bf16 = 784 B = 196 words (196 mod 32 = 4 -> conflict-free).
#define CTILEB (64 * 784)   // 50176 B
#define SMEM_CLS_TOTAL (4 * CTILEB + 64 * 68 * 4)   // 218112 B

__global__ __launch_bounds__(256, 1)
void cls_kernel(const float* __restrict__ bc1, const float* __restrict__ Wc2,
                const float* __restrict__ bc2, float* __restrict__ out) {
    extern __shared__ char smem[];
    char* Ah = smem;
    char* Al = smem + CTILEB;
    char* Wh = smem + 2 * CTILEB;
    char* Wl = smem + 3 * CTILEB;
    float* Zs = reinterpret_cast<float*>(smem + 4 * CTILEB);   // [64][68]

    int tid = threadIdx.x;
    int warp = tid >> 5, lane = tid & 31;
    int wr = warp >> 1, wc = warp & 1;
    int g = lane >> 2, t = lane & 3;
    int nodeBase = blockIdx.x * 64;

    // W1 copy: 2 splits x 64 n x 48 uint4
    for (int idx = tid; idx < 2 * 3072; idx += 256) {
        int sp = idx >= 3072;
        int r = idx - sp * 3072;
        int n = r / 48, k8 = r % 48;
        uint4 v = *reinterpret_cast<const uint4*>(g_W1b + (size_t)sp * H2 * JKD + (size_t)n * JKD + k8 * 8);
        *reinterpret_cast<uint4*>((sp ? Wl : Wh) + n * 784 + k8 * 16) = v;
    }
    // jk convert: 64 rows x 192 pairs
    for (int idx = tid; idx < 64 * 192; idx += 256) {
        int m = idx / 192, p = idx % 192;
        int node = nodeBase + m;
        float2 v = make_float2(0.f, 0.f);
        if (node < NN) v = *reinterpret_cast<const float2*>(g_jk + (size_t)node * JKD + 2 * p);
        __nv_bfloat162 h2 = __float22bfloat162_rn(v);
        float2 hf = __bfloat1622float2(h2);
        __nv_bfloat162 l2 = __float22bfloat162_rn(make_float2(v.x - hf.x, v.y - hf.y));
        *reinterpret_cast<uint32_t*>(Ah + m * 784 + p * 4) = *reinterpret_cast<uint32_t*>(&h2);
        *reinterpret_cast<uint32_t*>(Al + m * 784 + p * 4) = *reinterpret_cast<uint32_t*>(&l2);
    }
    __syncthreads();

    float acc[4][4];
#pragma unroll
    for (int ct = 0; ct < 4; ct++)
#pragma unroll
        for (int q = 0; q < 4; q++) acc[ct][q] = 0.f;

#pragma unroll
    for (int s = 0; s < 3; s++) {
        const char* A = (s == 2) ? Al : Ah;
        const char* W = (s == 1) ? Wl : Wh;
#pragma unroll 4
        for (int k16 = 0; k16 < 24; k16++) {
            int kb = k16 * 32 + t * 4;
            uint32_t a[4];
            const char* ab = A + (size_t)(wr * 16 + g) * 784 + kb;
            a[0] = *reinterpret_cast<const uint32_t*>(ab);
            a[1] = *reinterpret_cast<const uint32_t*>(ab + 8 * 784);
            a[2] = *reinterpret_cast<const uint32_t*>(ab + 16);
            a[3] = *reinterpret_cast<const uint32_t*>(ab + 8 * 784 + 16);
#pragma unroll
            for (int ct = 0; ct < 4; ct++) {
                const char* bbse = W + (size_t)(wc * 32 + ct * 8 + g) * 784 + kb;
                uint32_t bb[2];
                bb[0] = *reinterpret_cast<const uint32_t*>(bbse);
                bb[1] = *reinterpret_cast<const uint32_t*>(bbse + 16);
                mma16816(acc[ct], a, bb);
            }
        }
    }

    // z = relu(acc + bc1) into Zs
#pragma unroll
    for (int ct = 0; ct < 4; ct++) {
        int c = wc * 32 + ct * 8 + 2 * t;
        float b0 = bc1[c], b1 = bc1[c + 1];
        int m0 = wr * 16 + g, m1 = m0 + 8;
        Zs[m0 * 68 + c]     = fmaxf(acc[ct][0] + b0, 0.f);
        Zs[m0 * 68 + c + 1] = fmaxf(acc[ct][1] + b1, 0.f);
        Zs[m1 * 68 + c]     = fmaxf(acc[ct][2] + b0, 0.f);
        Zs[m1 * 68 + c + 1] = fmaxf(acc[ct][3] + b1, 0.f);
    }
    __syncthreads();

    if (tid < 128) {
        int m = tid >> 1, oc = tid & 1;
        int node = nodeBase + m;
        if (node < NN) {
            float sum = bc2[oc];
            const float* zrow = Zs + (size_t)m * 68;
#pragma unroll
            for (int j = 0; j < 64; j++) sum += zrow[j] * Wc2[j * 2 + oc];
            out[(size_t)node * 2 + oc] = sum;
        }
    }
}

// ---------------- host ----------------
extern "C" void kernel_launch(void* const* d_in, const int* in_sizes, int n_in,
                              void* d_out, int out_size) {
    const float* x     = (const float*)d_in[0];
    const void*  ei    = d_in[1];
    const float* Wl    = (const float*)d_in[2];
    const float* bl    = (const float*)d_in[3];
    const float* Wr    = (const float*)d_in[4];
    const float* gamma = (const float*)d_in[5];
    const float* beta  = (const float*)d_in[6];
    const float* rmean = (const float*)d_in[7];
    const float* rvar  = (const float*)d_in[8];
    const float* Wc1   = (const float*)d_in[9];
    const float* bc1   = (const float*)d_in[10];
    const float* Wc2   = (const float*)d_in[11];
    const float* bc2   = (const float*)d_in[12];
    float* out = (float*)d_out;

    cudaFuncSetAttribute(layer_kernel, cudaFuncAttributeMaxDynamicSharedMemorySize, SMEM_LAYER_TOTAL);
    cudaFuncSetAttribute(cls_kernel,   cudaFuncAttributeMaxDynamicSharedMemorySize, SMEM_CLS_TOTAL);

    detect_kernel<<<1, 32>>>((const int*)ei);
    wprep_kernel<<<(LL * 2 * DD * DD + 255) / 256, 256>>>(Wl, Wr);
    wprep2_kernel<<<(H2 * JKD + 255) / 256, 256>>>(Wc1);
    zero_deg_kernel<<<(NN + 255) / 256, 256>>>();
    deg_kernel<<<(EE + 255) / 256, 256>>>(ei);
    bsum_kernel<<<NB, 256>>>();
    bscan_kernel<<<1, 256>>>();
    offs_kernel<<<NB, 256>>>();
    fill_kernel<<<(EE + 255) / 256, 256>>>(ei);

    for (int layer = 0; layer < LL; layer++) {
        agg_kernel<<<(NN * 32 + 255) / 256, 256>>>(x, layer);
        layer_kernel<<<(NN + 127) / 128, 256, SMEM_LAYER_TOTAL>>>(x, layer, bl,
                                                                  gamma, beta, rmean, rvar);
    }
    cls_kernel<<<(NN + 63) / 64, 256, SMEM_CLS_TOTAL>>>(bc1, Wc2, bc2, out);
}